// round 5
// baseline (speedup 1.0000x reference)
#include <cuda_runtime.h>

#define H 64
#define DE 16
#define M_IN 144   // 2H + DE
#define U_IN 128   // 2H

#define N_MAX 50176
#define G_MAX 1024

typedef unsigned long long u64;

// Scratch (static device allocations; no cudaMalloc allowed)
__device__ float g_h[N_MAX * H];        // node features after each update (in-place)
__device__ float g_agg[N_MAX * H];      // per-layer aggregation target
__device__ float g_pooled[G_MAX * H];   // per-graph pooled sums
__device__ float g_counts[G_MAX];       // per-graph node counts

// ---------------------------------------------------------------------------
// Packed fp32x2 helpers (sm_100+): one instruction = two fp32 FMAs.
// ptxas never auto-fuses these from C++; PTX fma.rn.f32x2 is required.
// ---------------------------------------------------------------------------
__device__ __forceinline__ u64 fma2(u64 a, u64 b, u64 c) {
    u64 d;
    asm("fma.rn.f32x2 %0, %1, %2, %3;" : "=l"(d) : "l"(a), "l"(b), "l"(c));
    return d;
}
__device__ __forceinline__ u64 pack2(float v) {
    u64 d;
    unsigned int x = __float_as_uint(v);
    asm("mov.b64 %0, {%1, %1};" : "=l"(d) : "r"(x));
    return d;
}
__device__ __forceinline__ void unpack2(u64 in, float& lo, float& hi) {
    unsigned int a, b;
    asm("mov.b64 {%0, %1}, %2;" : "=r"(a), "=r"(b) : "l"(in));
    lo = __uint_as_float(a);
    hi = __uint_as_float(b);
}

// acc2[32] += (v,v) * wrow[0..63]  (32 packed FMAs, weights via LDS.128 pairs)
__device__ __forceinline__ void mac_row(u64* acc2, float v, const float* wrow) {
    u64 vv = pack2(v);
    const ulonglong2* w = reinterpret_cast<const ulonglong2*>(wrow);
    #pragma unroll
    for (int p = 0; p < 16; p++) {
        ulonglong2 wp = w[p];
        acc2[2 * p]     = fma2(vv, wp.x, acc2[2 * p]);
        acc2[2 * p + 1] = fma2(vv, wp.y, acc2[2 * p + 1]);
    }
}

__global__ void zero_kernel(float* __restrict__ p, int n) {
    int i = blockIdx.x * blockDim.x + threadIdx.x;
    if (i < n) p[i] = 0.0f;
}

// ---------------------------------------------------------------------------
// Message MLP + scatter-add.  One thread per edge, packed f32x2 math.
// m = relu([h[dst], h[src], ea] @ W1 + b1) @ W2 + b2 ; atomicAdd into agg[dst]
// ---------------------------------------------------------------------------
__global__ __launch_bounds__(256, 1) void msg_kernel(
    const float* __restrict__ h, const int* __restrict__ ei,
    const float* __restrict__ ea,
    const float* __restrict__ W1, const float* __restrict__ b1,
    const float* __restrict__ W2, const float* __restrict__ b2,
    int E)
{
    extern __shared__ float smem[];
    float* sW1 = smem;                 // 144*64
    float* sW2 = sW1 + M_IN * H;       // 64*64
    float* sb1 = sW2 + H * H;          // 64
    float* sb2 = sb1 + H;              // 64
    for (int i = threadIdx.x; i < M_IN * H; i += blockDim.x) sW1[i] = W1[i];
    for (int i = threadIdx.x; i < H * H; i += blockDim.x)   sW2[i] = W2[i];
    if (threadIdx.x < H) { sb1[threadIdx.x] = b1[threadIdx.x]; sb2[threadIdx.x] = b2[threadIdx.x]; }
    __syncthreads();

    int e = blockIdx.x * blockDim.x + threadIdx.x;
    if (e >= E) return;
    int src = ei[e];        // edge_index[0] = x_j
    int dst = ei[E + e];    // edge_index[1] = x_i (aggregation target)

    const float4* hi  = reinterpret_cast<const float4*>(h + (size_t)dst * H);
    const float4* hj  = reinterpret_cast<const float4*>(h + (size_t)src * H);
    const float4* eat = reinterpret_cast<const float4*>(ea + (size_t)e * DE);

    u64 acc2[32];
    const u64* b1p = reinterpret_cast<const u64*>(sb1);
    #pragma unroll
    for (int p = 0; p < 32; p++) acc2[p] = b1p[p];

    // --- first GEMM: 144 input rows ---
    #pragma unroll 2
    for (int k4 = 0; k4 < 16; k4++) {            // h[dst] rows 0..63
        float4 v4 = hi[k4];
        const float* w = sW1 + (k4 * 4) * H;
        mac_row(acc2, v4.x, w);
        mac_row(acc2, v4.y, w + H);
        mac_row(acc2, v4.z, w + 2 * H);
        mac_row(acc2, v4.w, w + 3 * H);
    }
    #pragma unroll 2
    for (int k4 = 0; k4 < 16; k4++) {            // h[src] rows 64..127
        float4 v4 = hj[k4];
        const float* w = sW1 + (64 + k4 * 4) * H;
        mac_row(acc2, v4.x, w);
        mac_row(acc2, v4.y, w + H);
        mac_row(acc2, v4.z, w + 2 * H);
        mac_row(acc2, v4.w, w + 3 * H);
    }
    #pragma unroll 2
    for (int k4 = 0; k4 < 4; k4++) {             // edge_attr rows 128..143
        float4 v4 = eat[k4];
        const float* w = sW1 + (128 + k4 * 4) * H;
        mac_row(acc2, v4.x, w);
        mac_row(acc2, v4.y, w + H);
        mac_row(acc2, v4.z, w + 2 * H);
        mac_row(acc2, v4.w, w + 3 * H);
    }

    // --- ReLU fused into second GEMM (64x64), packed outputs ---
    u64 o2[32];
    const u64* b2p = reinterpret_cast<const u64*>(sb2);
    #pragma unroll
    for (int p = 0; p < 32; p++) o2[p] = b2p[p];

    #pragma unroll 2
    for (int p = 0; p < 32; p++) {
        float a0, a1;
        unpack2(acc2[p], a0, a1);
        a0 = fmaxf(a0, 0.0f);
        a1 = fmaxf(a1, 0.0f);
        mac_row(o2, a0, sW2 + (2 * p) * H);
        mac_row(o2, a1, sW2 + (2 * p + 1) * H);
    }

    // --- scatter-add via float4 vector atomics (sm_90+) ---
    float4* aggrow = reinterpret_cast<float4*>(g_agg + (size_t)dst * H);
    #pragma unroll
    for (int q = 0; q < 16; q++) {
        float x0, x1, y0, y1;
        unpack2(o2[2 * q], x0, x1);
        unpack2(o2[2 * q + 1], y0, y1);
        atomicAdd(&aggrow[q], make_float4(x0, x1, y0, y1));
    }
}

// ---------------------------------------------------------------------------
// Update MLP.  One thread per node, packed f32x2 math.
// h = relu(relu([h, agg] @ uW1 + ub1) @ uW2 + ub2)   (writes g_h in place)
// ---------------------------------------------------------------------------
__global__ __launch_bounds__(256, 1) void upd_kernel(
    const float* __restrict__ hin,
    const float* __restrict__ W1, const float* __restrict__ b1,
    const float* __restrict__ W2, const float* __restrict__ b2,
    int N)
{
    extern __shared__ float smem[];
    float* sW1 = smem;                 // 128*64
    float* sW2 = sW1 + U_IN * H;       // 64*64
    float* sb1 = sW2 + H * H;
    float* sb2 = sb1 + H;
    for (int i = threadIdx.x; i < U_IN * H; i += blockDim.x) sW1[i] = W1[i];
    for (int i = threadIdx.x; i < H * H; i += blockDim.x)   sW2[i] = W2[i];
    if (threadIdx.x < H) { sb1[threadIdx.x] = b1[threadIdx.x]; sb2[threadIdx.x] = b2[threadIdx.x]; }
    __syncthreads();

    int n = blockIdx.x * blockDim.x + threadIdx.x;
    if (n >= N) return;

    const float4* hv = reinterpret_cast<const float4*>(hin + (size_t)n * H);
    const float4* av = reinterpret_cast<const float4*>(g_agg + (size_t)n * H);

    u64 acc2[32];
    const u64* b1p = reinterpret_cast<const u64*>(sb1);
    #pragma unroll
    for (int p = 0; p < 32; p++) acc2[p] = b1p[p];

    #pragma unroll 2
    for (int k4 = 0; k4 < 16; k4++) {            // h rows 0..63
        float4 v4 = hv[k4];
        const float* w = sW1 + (k4 * 4) * H;
        mac_row(acc2, v4.x, w);
        mac_row(acc2, v4.y, w + H);
        mac_row(acc2, v4.z, w + 2 * H);
        mac_row(acc2, v4.w, w + 3 * H);
    }
    #pragma unroll 2
    for (int k4 = 0; k4 < 16; k4++) {            // agg rows 64..127
        float4 v4 = av[k4];
        const float* w = sW1 + (64 + k4 * 4) * H;
        mac_row(acc2, v4.x, w);
        mac_row(acc2, v4.y, w + H);
        mac_row(acc2, v4.z, w + 2 * H);
        mac_row(acc2, v4.w, w + 3 * H);
    }

    u64 o2[32];
    const u64* b2p = reinterpret_cast<const u64*>(sb2);
    #pragma unroll
    for (int p = 0; p < 32; p++) o2[p] = b2p[p];

    #pragma unroll 2
    for (int p = 0; p < 32; p++) {
        float a0, a1;
        unpack2(acc2[p], a0, a1);
        a0 = fmaxf(a0, 0.0f);
        a1 = fmaxf(a1, 0.0f);
        mac_row(o2, a0, sW2 + (2 * p) * H);
        mac_row(o2, a1, sW2 + (2 * p + 1) * H);
    }

    float4* hout = reinterpret_cast<float4*>(g_h + (size_t)n * H);
    #pragma unroll
    for (int q = 0; q < 16; q++) {
        float x0, x1, y0, y1;
        unpack2(o2[2 * q], x0, x1);
        unpack2(o2[2 * q + 1], y0, y1);
        hout[q] = make_float4(fmaxf(x0, 0.0f), fmaxf(x1, 0.0f),
                              fmaxf(y0, 0.0f), fmaxf(y1, 0.0f));
    }
}

// ---------------------------------------------------------------------------
// Global mean-pool accumulation.  One thread per node.
// ---------------------------------------------------------------------------
__global__ void pool_kernel(const int* __restrict__ bidx, int N) {
    int n = blockIdx.x * blockDim.x + threadIdx.x;
    if (n >= N) return;
    int b = bidx[n];
    atomicAdd(&g_counts[b], 1.0f);
    const float4* row = reinterpret_cast<const float4*>(g_h + (size_t)n * H);
    float4* prow = reinterpret_cast<float4*>(g_pooled + (size_t)b * H);
    #pragma unroll
    for (int q = 0; q < 16; q++)
        atomicAdd(&prow[q], row[q]);
}

// ---------------------------------------------------------------------------
// Head: out = relu(pooled/count @ lin1 + b1) @ lin2 + b2.  One thread/graph.
// ---------------------------------------------------------------------------
__global__ void final_kernel(
    const float* __restrict__ l1w, const float* __restrict__ l1b,
    const float* __restrict__ l2w, const float* __restrict__ l2b,
    float* __restrict__ out, int G)
{
    __shared__ float sW[H * H];
    __shared__ float sb1[H];
    __shared__ float sw2[H];
    for (int i = threadIdx.x; i < H * H; i += blockDim.x) sW[i] = l1w[i];
    if (threadIdx.x < H) { sb1[threadIdx.x] = l1b[threadIdx.x]; sw2[threadIdx.x] = l2w[threadIdx.x]; }
    __syncthreads();

    int g = blockIdx.x * blockDim.x + threadIdx.x;
    if (g >= G) return;

    float inv = 1.0f / fmaxf(g_counts[g], 1.0f);
    float p[H];
    #pragma unroll
    for (int j = 0; j < H; j++) p[j] = g_pooled[g * H + j] * inv;

    float o = l2b[0];
    #pragma unroll 1
    for (int j2 = 0; j2 < H; j2++) {
        float hsum = sb1[j2];
        #pragma unroll
        for (int j = 0; j < H; j++) hsum += p[j] * sW[j * H + j2];
        o += fmaxf(hsum, 0.0f) * sw2[j2];
    }
    out[g] = o;
}

// ---------------------------------------------------------------------------
extern "C" void kernel_launch(void* const* d_in, const int* in_sizes, int n_in,
                              void* d_out, int out_size)
{
    const float* x    = (const float*)d_in[0];
    const int*   ei   = (const int*)d_in[1];     // int32 (JAX x64 disabled)
    const float* ea   = (const float*)d_in[2];
    const int*   bidx = (const int*)d_in[3];     // int32
    const float* mW1 = (const float*)d_in[4];
    const float* mb1 = (const float*)d_in[5];
    const float* mW2 = (const float*)d_in[6];
    const float* mb2 = (const float*)d_in[7];
    const float* uW1 = (const float*)d_in[8];
    const float* ub1 = (const float*)d_in[9];
    const float* uW2 = (const float*)d_in[10];
    const float* ub2 = (const float*)d_in[11];
    const float* l1w = (const float*)d_in[12];
    const float* l1b = (const float*)d_in[13];
    const float* l2w = (const float*)d_in[14];
    const float* l2b = (const float*)d_in[15];

    int N = in_sizes[0] / H;
    int E = in_sizes[1] / 2;
    int L = in_sizes[5] / H;     // mb1 is (L, H)
    int G = out_size;            // output is (G, 1) float32

    size_t msg_smem = (size_t)(M_IN * H + H * H + 2 * H) * sizeof(float);  // ~53.8 KB
    size_t upd_smem = (size_t)(U_IN * H + H * H + 2 * H) * sizeof(float);  // ~49.7 KB
    cudaFuncSetAttribute(msg_kernel, cudaFuncAttributeMaxDynamicSharedMemorySize, (int)msg_smem);
    cudaFuncSetAttribute(upd_kernel, cudaFuncAttributeMaxDynamicSharedMemorySize, (int)upd_smem);

    float *h_ptr, *agg_ptr, *pooled_ptr, *counts_ptr;
    cudaGetSymbolAddress((void**)&h_ptr,      g_h);
    cudaGetSymbolAddress((void**)&agg_ptr,    g_agg);
    cudaGetSymbolAddress((void**)&pooled_ptr, g_pooled);
    cudaGetSymbolAddress((void**)&counts_ptr, g_counts);

    const int T = 256;
    for (int l = 0; l < L; l++) {
        const float* hin = (l == 0) ? x : h_ptr;
        zero_kernel<<<(N * H + T - 1) / T, T>>>(agg_ptr, N * H);
        msg_kernel<<<(E + T - 1) / T, T, msg_smem>>>(
            hin, ei, ea,
            mW1 + (size_t)l * M_IN * H, mb1 + (size_t)l * H,
            mW2 + (size_t)l * H * H,    mb2 + (size_t)l * H, E);
        upd_kernel<<<(N + T - 1) / T, T, upd_smem>>>(
            hin,
            uW1 + (size_t)l * U_IN * H, ub1 + (size_t)l * H,
            uW2 + (size_t)l * H * H,    ub2 + (size_t)l * H, N);
    }

    zero_kernel<<<(G * H + T - 1) / T, T>>>(pooled_ptr, G * H);
    zero_kernel<<<(G + T - 1) / T, T>>>(counts_ptr, G);
    pool_kernel<<<(N + T - 1) / T, T>>>(bidx, N);
    final_kernel<<<(G + 127) / 128, 128>>>(l1w, l1b, l2w, l2b, (float*)d_out, G);
}

// round 8
// speedup vs baseline: 1.5165x; 1.5165x over previous
#include <cuda_runtime.h>

#define H 64
#define DE 16
#define M_IN 144   // 2H + DE
#define U_IN 128   // 2H

#define N_MAX 50176
#define G_MAX 1024

// Scratch (static device allocations; no cudaMalloc allowed)
__device__ float g_h[N_MAX * H];        // node features after each update (in-place)
__device__ float g_agg[N_MAX * H];      // per-layer aggregation target (re-zeroed by upd)
__device__ float g_pooled[G_MAX * H];   // per-graph pooled sums (re-zeroed by final)
__device__ float g_counts[G_MAX];       // per-graph node counts (re-zeroed by final)

__global__ void shim_kernel() {}        // launch-index shim so ncu window hits msg_kernel

// ---------------------------------------------------------------------------
// Message MLP + scatter-add.  TWO edges per thread (weight LDS amortized 2x).
// m = relu([h[dst], h[src], ea] @ W1 + b1) @ W2 + b2 ; atomicAdd into agg[dst]
// ---------------------------------------------------------------------------
__global__ __launch_bounds__(256) void msg_kernel(
    const float* __restrict__ h, const int* __restrict__ ei,
    const float* __restrict__ ea,
    const float* __restrict__ W1, const float* __restrict__ b1,
    const float* __restrict__ W2, const float* __restrict__ b2,
    int E)
{
    extern __shared__ float smem[];
    float* sW1 = smem;                 // 144*64
    float* sW2 = sW1 + M_IN * H;       // 64*64
    float* sb1 = sW2 + H * H;          // 64
    float* sb2 = sb1 + H;              // 64
    for (int i = threadIdx.x; i < M_IN * H; i += blockDim.x) sW1[i] = W1[i];
    for (int i = threadIdx.x; i < H * H; i += blockDim.x)   sW2[i] = W2[i];
    if (threadIdx.x < H) { sb1[threadIdx.x] = b1[threadIdx.x]; sb2[threadIdx.x] = b2[threadIdx.x]; }
    __syncthreads();

    int t  = blockIdx.x * blockDim.x + threadIdx.x;
    int e0 = 2 * t;
    int e1 = 2 * t + 1;
    if (e0 >= E) return;
    bool has1 = (e1 < E);
    int e1s = has1 ? e1 : e0;            // safe index for gathers when edge1 absent

    int src0 = ei[e0],       dst0 = ei[E + e0];
    int src1 = ei[e1s],      dst1 = ei[E + e1s];

    const float4* hi0 = reinterpret_cast<const float4*>(h + (size_t)dst0 * H);
    const float4* hj0 = reinterpret_cast<const float4*>(h + (size_t)src0 * H);
    const float4* hi1 = reinterpret_cast<const float4*>(h + (size_t)dst1 * H);
    const float4* hj1 = reinterpret_cast<const float4*>(h + (size_t)src1 * H);
    const float4* ea0 = reinterpret_cast<const float4*>(ea + (size_t)e0 * DE);
    const float4* ea1 = reinterpret_cast<const float4*>(ea + (size_t)e1s * DE);

    float acc0[H], acc1[H];
    #pragma unroll
    for (int j = 0; j < H; j++) { float b = sb1[j]; acc0[j] = b; acc1[j] = b; }

    // --- first GEMM: 144 input rows, shared weight loads for both edges ---
    #pragma unroll 1
    for (int k4 = 0; k4 < 16; k4++) {            // h[dst] rows 0..63
        float4 a4 = hi0[k4], c4 = hi1[k4];
        float va[4] = {a4.x, a4.y, a4.z, a4.w};
        float vb[4] = {c4.x, c4.y, c4.z, c4.w};
        const float* w = sW1 + (k4 * 4) * H;
        #pragma unroll
        for (int u = 0; u < 4; u++)
            #pragma unroll
            for (int j = 0; j < H; j++) {
                float wv = w[u * H + j];
                acc0[j] += va[u] * wv;
                acc1[j] += vb[u] * wv;
            }
    }
    #pragma unroll 1
    for (int k4 = 0; k4 < 16; k4++) {            // h[src] rows 64..127
        float4 a4 = hj0[k4], c4 = hj1[k4];
        float va[4] = {a4.x, a4.y, a4.z, a4.w};
        float vb[4] = {c4.x, c4.y, c4.z, c4.w};
        const float* w = sW1 + (64 + k4 * 4) * H;
        #pragma unroll
        for (int u = 0; u < 4; u++)
            #pragma unroll
            for (int j = 0; j < H; j++) {
                float wv = w[u * H + j];
                acc0[j] += va[u] * wv;
                acc1[j] += vb[u] * wv;
            }
    }
    #pragma unroll 1
    for (int k4 = 0; k4 < 4; k4++) {             // edge_attr rows 128..143
        float4 a4 = ea0[k4], c4 = ea1[k4];
        float va[4] = {a4.x, a4.y, a4.z, a4.w};
        float vb[4] = {c4.x, c4.y, c4.z, c4.w};
        const float* w = sW1 + (128 + k4 * 4) * H;
        #pragma unroll
        for (int u = 0; u < 4; u++)
            #pragma unroll
            for (int j = 0; j < H; j++) {
                float wv = w[u * H + j];
                acc0[j] += va[u] * wv;
                acc1[j] += vb[u] * wv;
            }
    }

    #pragma unroll
    for (int j = 0; j < H; j++) {
        acc0[j] = fmaxf(acc0[j], 0.0f);
        acc1[j] = fmaxf(acc1[j], 0.0f);
    }

    // --- second GEMM (64x64) + scatter-add, 4 outputs at a time, both edges ---
    float* row0 = g_agg + (size_t)dst0 * H;
    float* row1 = g_agg + (size_t)dst1 * H;
    #pragma unroll 1
    for (int j2 = 0; j2 < H; j2 += 4) {
        float p0 = sb2[j2], p1 = sb2[j2 + 1], p2 = sb2[j2 + 2], p3 = sb2[j2 + 3];
        float q0 = p0, q1 = p1, q2 = p2, q3 = p3;
        #pragma unroll
        for (int j = 0; j < H; j++) {
            float4 w = *reinterpret_cast<const float4*>(sW2 + j * H + j2);
            float a = acc0[j], c = acc1[j];
            p0 += a * w.x; p1 += a * w.y; p2 += a * w.z; p3 += a * w.w;
            q0 += c * w.x; q1 += c * w.y; q2 += c * w.z; q3 += c * w.w;
        }
        atomicAdd(reinterpret_cast<float4*>(row0 + j2), make_float4(p0, p1, p2, p3));
        if (has1)
            atomicAdd(reinterpret_cast<float4*>(row1 + j2), make_float4(q0, q1, q2, q3));
    }
}

// ---------------------------------------------------------------------------
// Update MLP.  One thread per node.  Re-zeroes its g_agg row after use.
// h = relu(relu([h, agg] @ uW1 + ub1) @ uW2 + ub2)   (writes g_h in place)
// ---------------------------------------------------------------------------
__global__ __launch_bounds__(256, 2) void upd_kernel(
    const float* __restrict__ hin,
    const float* __restrict__ W1, const float* __restrict__ b1,
    const float* __restrict__ W2, const float* __restrict__ b2,
    int N)
{
    extern __shared__ float smem[];
    float* sW1 = smem;                 // 128*64
    float* sW2 = sW1 + U_IN * H;       // 64*64
    float* sb1 = sW2 + H * H;
    float* sb2 = sb1 + H;
    for (int i = threadIdx.x; i < U_IN * H; i += blockDim.x) sW1[i] = W1[i];
    for (int i = threadIdx.x; i < H * H; i += blockDim.x)   sW2[i] = W2[i];
    if (threadIdx.x < H) { sb1[threadIdx.x] = b1[threadIdx.x]; sb2[threadIdx.x] = b2[threadIdx.x]; }
    __syncthreads();

    int n = blockIdx.x * blockDim.x + threadIdx.x;
    if (n >= N) return;

    const float4* hv = reinterpret_cast<const float4*>(hin + (size_t)n * H);
    float4*       av = reinterpret_cast<float4*>(g_agg + (size_t)n * H);

    float acc[H];
    #pragma unroll
    for (int j = 0; j < H; j++) acc[j] = sb1[j];

    #pragma unroll 2
    for (int k4 = 0; k4 < 16; k4++) {            // h rows 0..63
        float4 v4 = hv[k4];
        float v[4] = {v4.x, v4.y, v4.z, v4.w};
        const float* w = sW1 + (k4 * 4) * H;
        #pragma unroll
        for (int u = 0; u < 4; u++)
            #pragma unroll
            for (int j = 0; j < H; j++)
                acc[j] += v[u] * w[u * H + j];
    }
    #pragma unroll 2
    for (int k4 = 0; k4 < 16; k4++) {            // agg rows 64..127
        float4 v4 = av[k4];
        float v[4] = {v4.x, v4.y, v4.z, v4.w};
        const float* w = sW1 + (64 + k4 * 4) * H;
        #pragma unroll
        for (int u = 0; u < 4; u++)
            #pragma unroll
            for (int j = 0; j < H; j++)
                acc[j] += v[u] * w[u * H + j];
    }

    // re-zero this node's agg row for the next layer / next graph replay
    float4 z4 = make_float4(0.0f, 0.0f, 0.0f, 0.0f);
    #pragma unroll
    for (int k4 = 0; k4 < 16; k4++) av[k4] = z4;

    #pragma unroll
    for (int j = 0; j < H; j++) acc[j] = fmaxf(acc[j], 0.0f);

    float* hout = g_h + (size_t)n * H;
    #pragma unroll 1
    for (int j2 = 0; j2 < H; j2 += 4) {
        float o0 = sb2[j2], o1 = sb2[j2 + 1], o2 = sb2[j2 + 2], o3 = sb2[j2 + 3];
        #pragma unroll
        for (int j = 0; j < H; j++) {
            float a = acc[j];
            float4 w = *reinterpret_cast<const float4*>(sW2 + j * H + j2);
            o0 += a * w.x; o1 += a * w.y; o2 += a * w.z; o3 += a * w.w;
        }
        float4 r;
        r.x = fmaxf(o0, 0.0f); r.y = fmaxf(o1, 0.0f);
        r.z = fmaxf(o2, 0.0f); r.w = fmaxf(o3, 0.0f);
        *reinterpret_cast<float4*>(hout + j2) = r;
    }
}

// ---------------------------------------------------------------------------
// Global mean-pool accumulation.  One thread per node.
// ---------------------------------------------------------------------------
__global__ void pool_kernel(const int* __restrict__ bidx, int N) {
    int n = blockIdx.x * blockDim.x + threadIdx.x;
    if (n >= N) return;
    int b = bidx[n];
    atomicAdd(&g_counts[b], 1.0f);
    const float4* row = reinterpret_cast<const float4*>(g_h + (size_t)n * H);
    float4* prow = reinterpret_cast<float4*>(g_pooled + (size_t)b * H);
    #pragma unroll
    for (int q = 0; q < 16; q++)
        atomicAdd(&prow[q], row[q]);
}

// ---------------------------------------------------------------------------
// Head: out = relu(pooled/count @ lin1 + b1) @ lin2 + b2.  One thread/graph.
// Re-zeroes g_pooled / g_counts for the next graph replay.
// ---------------------------------------------------------------------------
__global__ void final_kernel(
    const float* __restrict__ l1w, const float* __restrict__ l1b,
    const float* __restrict__ l2w, const float* __restrict__ l2b,
    float* __restrict__ out, int G)
{
    __shared__ float sW[H * H];
    __shared__ float sb1[H];
    __shared__ float sw2[H];
    for (int i = threadIdx.x; i < H * H; i += blockDim.x) sW[i] = l1w[i];
    if (threadIdx.x < H) { sb1[threadIdx.x] = l1b[threadIdx.x]; sw2[threadIdx.x] = l2w[threadIdx.x]; }
    __syncthreads();

    int g = blockIdx.x * blockDim.x + threadIdx.x;
    if (g >= G) return;

    float inv = 1.0f / fmaxf(g_counts[g], 1.0f);
    float p[H];
    #pragma unroll
    for (int j = 0; j < H; j++) p[j] = g_pooled[g * H + j] * inv;

    // re-zero pooled state for next replay
    g_counts[g] = 0.0f;
    #pragma unroll
    for (int j = 0; j < H; j++) g_pooled[g * H + j] = 0.0f;

    float o = l2b[0];
    #pragma unroll 1
    for (int j2 = 0; j2 < H; j2++) {
        float hsum = sb1[j2];
        #pragma unroll
        for (int j = 0; j < H; j++) hsum += p[j] * sW[j * H + j2];
        o += fmaxf(hsum, 0.0f) * sw2[j2];
    }
    out[g] = o;
}

// ---------------------------------------------------------------------------
extern "C" void kernel_launch(void* const* d_in, const int* in_sizes, int n_in,
                              void* d_out, int out_size)
{
    const float* x    = (const float*)d_in[0];
    const int*   ei   = (const int*)d_in[1];     // int32 (JAX x64 disabled)
    const float* ea   = (const float*)d_in[2];
    const int*   bidx = (const int*)d_in[3];     // int32
    const float* mW1 = (const float*)d_in[4];
    const float* mb1 = (const float*)d_in[5];
    const float* mW2 = (const float*)d_in[6];
    const float* mb2 = (const float*)d_in[7];
    const float* uW1 = (const float*)d_in[8];
    const float* ub1 = (const float*)d_in[9];
    const float* uW2 = (const float*)d_in[10];
    const float* ub2 = (const float*)d_in[11];
    const float* l1w = (const float*)d_in[12];
    const float* l1b = (const float*)d_in[13];
    const float* l2w = (const float*)d_in[14];
    const float* l2b = (const float*)d_in[15];

    int N = in_sizes[0] / H;
    int E = in_sizes[1] / 2;
    int L = in_sizes[5] / H;     // mb1 is (L, H)
    int G = out_size;            // output is (G, 1) float32

    size_t msg_smem = (size_t)(M_IN * H + H * H + 2 * H) * sizeof(float);  // ~53.8 KB
    size_t upd_smem = (size_t)(U_IN * H + H * H + 2 * H) * sizeof(float);  // ~49.7 KB
    cudaFuncSetAttribute(msg_kernel, cudaFuncAttributeMaxDynamicSharedMemorySize, (int)msg_smem);
    cudaFuncSetAttribute(upd_kernel, cudaFuncAttributeMaxDynamicSharedMemorySize, (int)upd_smem);

    const int T = 256;
    int npairs = (E + 1) / 2;
    for (int l = 0; l < L; l++) {
        const float* hin = (l == 0) ? x : (const float*)nullptr;
        // shims before the last layer's msg so the ncu capture window (launch
        // index ~6) lands on msg_kernel instead of a trivial kernel
        if (l == L - 1) { shim_kernel<<<1, 32>>>(); shim_kernel<<<1, 32>>>(); }
        float* h_ptr;
        cudaGetSymbolAddress((void**)&h_ptr, g_h);
        const float* hsrc = (l == 0) ? x : h_ptr;
        msg_kernel<<<(npairs + T - 1) / T, T, msg_smem>>>(
            hsrc, ei, ea,
            mW1 + (size_t)l * M_IN * H, mb1 + (size_t)l * H,
            mW2 + (size_t)l * H * H,    mb2 + (size_t)l * H, E);
        upd_kernel<<<(N + T - 1) / T, T, upd_smem>>>(
            hsrc,
            uW1 + (size_t)l * U_IN * H, ub1 + (size_t)l * H,
            uW2 + (size_t)l * H * H,    ub2 + (size_t)l * H, N);
        (void)hin;
    }

    pool_kernel<<<(N + T - 1) / T, T>>>(bidx, N);
    final_kernel<<<(G + 127) / 128, 128>>>(l1w, l1b, l2w, l2b, (float*)d_out, G);
}

// round 9
// speedup vs baseline: 1.7739x; 1.1697x over previous
#include <cuda_runtime.h>

#define H 64
#define DE 16
#define M_IN 144   // 2H + DE
#define U_IN 128   // 2H

#define N_MAX 50176
#define G_MAX 1024

// Scratch (static device allocations; no cudaMalloc allowed)
__device__ float g_h[N_MAX * H];        // node features after each update (in-place)
__device__ float g_agg[N_MAX * H];      // per-layer sum of relu(z1) (re-zeroed by upd)
__device__ float g_deg[N_MAX];          // node in-degree (recomputed each replay)
__device__ float g_pooled[G_MAX * H];   // per-graph pooled sums (re-zeroed by final)
__device__ float g_counts[G_MAX];       // per-graph node counts (re-zeroed by final)

__global__ void shim_kernel() {}        // launch-index shim so ncu window hits msg_kernel

__global__ void zero_kernel(float* __restrict__ p, int n) {
    int i = blockIdx.x * blockDim.x + threadIdx.x;
    if (i < n) p[i] = 0.0f;
}

// degree: one atomic per edge (spread addresses -> near LSU floor)
__global__ void deg_kernel(const int* __restrict__ ei, int E) {
    int e = blockIdx.x * blockDim.x + threadIdx.x;
    if (e < E) atomicAdd(&g_deg[ei[E + e]], 1.0f);
}

// ---------------------------------------------------------------------------
// Message stage, GEMM1 ONLY (GEMM2 moved to node side — it commutes with the
// linear scatter-sum).  TWO edges per thread; weight LDS amortized 2x.
// scatter: agg1[dst] += relu([h[dst], h[src], ea] @ W1 + b1)
// ---------------------------------------------------------------------------
__global__ __launch_bounds__(128) void msg_kernel(
    const float* __restrict__ h, const int* __restrict__ ei,
    const float* __restrict__ ea,
    const float* __restrict__ W1, const float* __restrict__ b1,
    int E)
{
    extern __shared__ float smem[];
    float* sW1 = smem;                 // 144*64
    float* sb1 = sW1 + M_IN * H;       // 64
    for (int i = threadIdx.x; i < M_IN * H; i += blockDim.x) sW1[i] = W1[i];
    if (threadIdx.x < H) sb1[threadIdx.x] = b1[threadIdx.x];
    __syncthreads();

    int t  = blockIdx.x * blockDim.x + threadIdx.x;
    int e0 = 2 * t;
    int e1 = 2 * t + 1;
    if (e0 >= E) return;
    bool has1 = (e1 < E);
    int e1s = has1 ? e1 : e0;            // safe index for gathers when edge1 absent

    int src0 = ei[e0],  dst0 = ei[E + e0];
    int src1 = ei[e1s], dst1 = ei[E + e1s];

    const float4* hi0 = reinterpret_cast<const float4*>(h + (size_t)dst0 * H);
    const float4* hj0 = reinterpret_cast<const float4*>(h + (size_t)src0 * H);
    const float4* hi1 = reinterpret_cast<const float4*>(h + (size_t)dst1 * H);
    const float4* hj1 = reinterpret_cast<const float4*>(h + (size_t)src1 * H);
    const float4* ea0 = reinterpret_cast<const float4*>(ea + (size_t)e0 * DE);
    const float4* ea1 = reinterpret_cast<const float4*>(ea + (size_t)e1s * DE);

    float acc0[H], acc1[H];
    #pragma unroll
    for (int j = 0; j < H; j++) { float b = sb1[j]; acc0[j] = b; acc1[j] = b; }

    #pragma unroll 1
    for (int k4 = 0; k4 < 16; k4++) {            // h[dst] rows 0..63
        float4 a4 = hi0[k4], c4 = hi1[k4];
        float va[4] = {a4.x, a4.y, a4.z, a4.w};
        float vb[4] = {c4.x, c4.y, c4.z, c4.w};
        const float* w = sW1 + (k4 * 4) * H;
        #pragma unroll
        for (int u = 0; u < 4; u++)
            #pragma unroll
            for (int j = 0; j < H; j++) {
                float wv = w[u * H + j];
                acc0[j] += va[u] * wv;
                acc1[j] += vb[u] * wv;
            }
    }
    #pragma unroll 1
    for (int k4 = 0; k4 < 16; k4++) {            // h[src] rows 64..127
        float4 a4 = hj0[k4], c4 = hj1[k4];
        float va[4] = {a4.x, a4.y, a4.z, a4.w};
        float vb[4] = {c4.x, c4.y, c4.z, c4.w};
        const float* w = sW1 + (64 + k4 * 4) * H;
        #pragma unroll
        for (int u = 0; u < 4; u++)
            #pragma unroll
            for (int j = 0; j < H; j++) {
                float wv = w[u * H + j];
                acc0[j] += va[u] * wv;
                acc1[j] += vb[u] * wv;
            }
    }
    #pragma unroll 1
    for (int k4 = 0; k4 < 4; k4++) {             // edge_attr rows 128..143
        float4 a4 = ea0[k4], c4 = ea1[k4];
        float va[4] = {a4.x, a4.y, a4.z, a4.w};
        float vb[4] = {c4.x, c4.y, c4.z, c4.w};
        const float* w = sW1 + (128 + k4 * 4) * H;
        #pragma unroll
        for (int u = 0; u < 4; u++)
            #pragma unroll
            for (int j = 0; j < H; j++) {
                float wv = w[u * H + j];
                acc0[j] += va[u] * wv;
                acc1[j] += vb[u] * wv;
            }
    }

    // scatter relu(z1) directly — no per-edge GEMM2
    float* row0 = g_agg + (size_t)dst0 * H;
    float* row1 = g_agg + (size_t)dst1 * H;
    #pragma unroll
    for (int q = 0; q < 16; q++) {
        float4 v0 = make_float4(fmaxf(acc0[4*q], 0.0f),   fmaxf(acc0[4*q+1], 0.0f),
                                fmaxf(acc0[4*q+2], 0.0f), fmaxf(acc0[4*q+3], 0.0f));
        atomicAdd(reinterpret_cast<float4*>(row0 + 4*q), v0);
    }
    if (has1) {
        #pragma unroll
        for (int q = 0; q < 16; q++) {
            float4 v1 = make_float4(fmaxf(acc1[4*q], 0.0f),   fmaxf(acc1[4*q+1], 0.0f),
                                    fmaxf(acc1[4*q+2], 0.0f), fmaxf(acc1[4*q+3], 0.0f));
            atomicAdd(reinterpret_cast<float4*>(row1 + 4*q), v1);
        }
    }
}

// ---------------------------------------------------------------------------
// Update stage (now includes the deferred message GEMM2).  One thread/node.
//   a2  = agg1[n] @ mW2 + deg[n]*mb2          (deferred GEMM2)
//   t   = relu([h, a2] @ uW1 + ub1)
//   h   = relu(t @ uW2 + ub2)
// Re-zeroes its g_agg row after use.
// ---------------------------------------------------------------------------
__global__ __launch_bounds__(128) void upd_kernel(
    const float* __restrict__ hin,
    const float* __restrict__ mW2, const float* __restrict__ mb2,
    const float* __restrict__ W1,  const float* __restrict__ b1,
    const float* __restrict__ W2,  const float* __restrict__ b2,
    int N)
{
    extern __shared__ float smem[];
    float* sM2  = smem;                 // 64*64  (message W2)
    float* sW1  = sM2 + H * H;          // 128*64
    float* sW2  = sW1 + U_IN * H;       // 64*64
    float* smb2 = sW2 + H * H;          // 64
    float* sb1  = smb2 + H;             // 64
    float* sb2  = sb1 + H;              // 64
    for (int i = threadIdx.x; i < H * H; i += blockDim.x)    sM2[i] = mW2[i];
    for (int i = threadIdx.x; i < U_IN * H; i += blockDim.x) sW1[i] = W1[i];
    for (int i = threadIdx.x; i < H * H; i += blockDim.x)    sW2[i] = W2[i];
    if (threadIdx.x < H) {
        smb2[threadIdx.x] = mb2[threadIdx.x];
        sb1[threadIdx.x]  = b1[threadIdx.x];
        sb2[threadIdx.x]  = b2[threadIdx.x];
    }
    __syncthreads();

    int n = blockIdx.x * blockDim.x + threadIdx.x;
    if (n >= N) return;

    const float4* hv = reinterpret_cast<const float4*>(hin + (size_t)n * H);
    float4*       av = reinterpret_cast<float4*>(g_agg + (size_t)n * H);
    float deg = g_deg[n];

    // --- phase 1: deferred GEMM2: a2 = agg1 @ mW2 + deg*mb2 ---
    float a2[H];
    #pragma unroll
    for (int j = 0; j < H; j++) a2[j] = deg * smb2[j];
    #pragma unroll 2
    for (int k4 = 0; k4 < 16; k4++) {
        float4 v4 = av[k4];
        float v[4] = {v4.x, v4.y, v4.z, v4.w};
        const float* w = sM2 + (k4 * 4) * H;
        #pragma unroll
        for (int u = 0; u < 4; u++)
            #pragma unroll
            for (int j = 0; j < H; j++)
                a2[j] += v[u] * w[u * H + j];
    }

    // re-zero this node's agg row for the next layer / next graph replay
    float4 z4 = make_float4(0.0f, 0.0f, 0.0f, 0.0f);
    #pragma unroll
    for (int k4 = 0; k4 < 16; k4++) av[k4] = z4;

    // --- phase 2: t = relu([h, a2] @ uW1 + ub1) ---
    float acc[H];
    #pragma unroll
    for (int j = 0; j < H; j++) acc[j] = sb1[j];

    #pragma unroll 2
    for (int k4 = 0; k4 < 16; k4++) {            // h rows 0..63
        float4 v4 = hv[k4];
        float v[4] = {v4.x, v4.y, v4.z, v4.w};
        const float* w = sW1 + (k4 * 4) * H;
        #pragma unroll
        for (int u = 0; u < 4; u++)
            #pragma unroll
            for (int j = 0; j < H; j++)
                acc[j] += v[u] * w[u * H + j];
    }
    #pragma unroll 1
    for (int k = 0; k < H; k++) {                // a2 rows 64..127 (values in regs)
        float v = a2[k];
        const float* w = sW1 + (64 + k) * H;
        #pragma unroll
        for (int j = 0; j < H; j++)
            acc[j] += v * w[j];
    }

    #pragma unroll
    for (int j = 0; j < H; j++) acc[j] = fmaxf(acc[j], 0.0f);

    // --- phase 3: h = relu(t @ uW2 + ub2) ---
    float* hout = g_h + (size_t)n * H;
    #pragma unroll 1
    for (int j2 = 0; j2 < H; j2 += 4) {
        float o0 = sb2[j2], o1 = sb2[j2 + 1], o2 = sb2[j2 + 2], o3 = sb2[j2 + 3];
        #pragma unroll
        for (int j = 0; j < H; j++) {
            float a = acc[j];
            float4 w = *reinterpret_cast<const float4*>(sW2 + j * H + j2);
            o0 += a * w.x; o1 += a * w.y; o2 += a * w.z; o3 += a * w.w;
        }
        float4 r;
        r.x = fmaxf(o0, 0.0f); r.y = fmaxf(o1, 0.0f);
        r.z = fmaxf(o2, 0.0f); r.w = fmaxf(o3, 0.0f);
        *reinterpret_cast<float4*>(hout + j2) = r;
    }
}

// ---------------------------------------------------------------------------
// Global mean-pool accumulation.  One thread per node.
// ---------------------------------------------------------------------------
__global__ void pool_kernel(const int* __restrict__ bidx, int N) {
    int n = blockIdx.x * blockDim.x + threadIdx.x;
    if (n >= N) return;
    int b = bidx[n];
    atomicAdd(&g_counts[b], 1.0f);
    const float4* row = reinterpret_cast<const float4*>(g_h + (size_t)n * H);
    float4* prow = reinterpret_cast<float4*>(g_pooled + (size_t)b * H);
    #pragma unroll
    for (int q = 0; q < 16; q++)
        atomicAdd(&prow[q], row[q]);
}

// ---------------------------------------------------------------------------
// Head: out = relu(pooled/count @ lin1 + b1) @ lin2 + b2.  One thread/graph.
// Re-zeroes g_pooled / g_counts for the next graph replay.
// ---------------------------------------------------------------------------
__global__ void final_kernel(
    const float* __restrict__ l1w, const float* __restrict__ l1b,
    const float* __restrict__ l2w, const float* __restrict__ l2b,
    float* __restrict__ out, int G)
{
    __shared__ float sW[H * H];
    __shared__ float sb1[H];
    __shared__ float sw2[H];
    for (int i = threadIdx.x; i < H * H; i += blockDim.x) sW[i] = l1w[i];
    if (threadIdx.x < H) { sb1[threadIdx.x] = l1b[threadIdx.x]; sw2[threadIdx.x] = l2w[threadIdx.x]; }
    __syncthreads();

    int g = blockIdx.x * blockDim.x + threadIdx.x;
    if (g >= G) return;

    float inv = 1.0f / fmaxf(g_counts[g], 1.0f);
    float p[H];
    #pragma unroll
    for (int j = 0; j < H; j++) p[j] = g_pooled[g * H + j] * inv;

    // re-zero pooled state for next replay
    g_counts[g] = 0.0f;
    #pragma unroll
    for (int j = 0; j < H; j++) g_pooled[g * H + j] = 0.0f;

    float o = l2b[0];
    #pragma unroll 1
    for (int j2 = 0; j2 < H; j2++) {
        float hsum = sb1[j2];
        #pragma unroll
        for (int j = 0; j < H; j++) hsum += p[j] * sW[j * H + j2];
        o += fmaxf(hsum, 0.0f) * sw2[j2];
    }
    out[g] = o;
}

// ---------------------------------------------------------------------------
extern "C" void kernel_launch(void* const* d_in, const int* in_sizes, int n_in,
                              void* d_out, int out_size)
{
    const float* x    = (const float*)d_in[0];
    const int*   ei   = (const int*)d_in[1];     // int32 (JAX x64 disabled)
    const float* ea   = (const float*)d_in[2];
    const int*   bidx = (const int*)d_in[3];     // int32
    const float* mW1 = (const float*)d_in[4];
    const float* mb1 = (const float*)d_in[5];
    const float* mW2 = (const float*)d_in[6];
    const float* mb2 = (const float*)d_in[7];
    const float* uW1 = (const float*)d_in[8];
    const float* ub1 = (const float*)d_in[9];
    const float* uW2 = (const float*)d_in[10];
    const float* ub2 = (const float*)d_in[11];
    const float* l1w = (const float*)d_in[12];
    const float* l1b = (const float*)d_in[13];
    const float* l2w = (const float*)d_in[14];
    const float* l2b = (const float*)d_in[15];

    int N = in_sizes[0] / H;
    int E = in_sizes[1] / 2;
    int L = in_sizes[5] / H;     // mb1 is (L, H)
    int G = out_size;            // output is (G, 1) float32

    size_t msg_smem = (size_t)(M_IN * H + H) * sizeof(float);                     // ~37 KB
    size_t upd_smem = (size_t)(H * H + U_IN * H + H * H + 3 * H) * sizeof(float); // ~66 KB
    cudaFuncSetAttribute(msg_kernel, cudaFuncAttributeMaxDynamicSharedMemorySize, (int)msg_smem);
    cudaFuncSetAttribute(upd_kernel, cudaFuncAttributeMaxDynamicSharedMemorySize, (int)upd_smem);

    float *h_ptr, *deg_ptr;
    cudaGetSymbolAddress((void**)&h_ptr,  g_h);
    cudaGetSymbolAddress((void**)&deg_ptr, g_deg);

    const int T = 128;
    int npairs = (E + 1) / 2;

    // degree (fresh each replay, deterministic)
    zero_kernel<<<(N + 255) / 256, 256>>>(deg_ptr, N);
    deg_kernel<<<(E + 255) / 256, 256>>>(ei, E);
    shim_kernel<<<1, 32>>>();   // aligns ncu -s 5 -c 1 onto layer-1 msg_kernel

    for (int l = 0; l < L; l++) {
        const float* hsrc = (l == 0) ? x : h_ptr;
        msg_kernel<<<(npairs + T - 1) / T, T, msg_smem>>>(
            hsrc, ei, ea,
            mW1 + (size_t)l * M_IN * H, mb1 + (size_t)l * H, E);
        upd_kernel<<<(N + T - 1) / T, T, upd_smem>>>(
            hsrc,
            mW2 + (size_t)l * H * H,    mb2 + (size_t)l * H,
            uW1 + (size_t)l * U_IN * H, ub1 + (size_t)l * H,
            uW2 + (size_t)l * H * H,    ub2 + (size_t)l * H, N);
    }

    pool_kernel<<<(N + 255) / 256, 256>>>(bidx, N);
    final_kernel<<<(G + 127) / 128, 128>>>(l1w, l1b, l2w, l2b, (float*)d_out, G);
}

// round 11
// speedup vs baseline: 3.0153x; 1.6999x over previous
#include <cuda_runtime.h>

#define H 64
#define DE 16
#define U_IN 128   // 2H

#define N_MAX 50176
#define G_MAX 1024

// Scratch (static device allocations; no cudaMalloc allowed)
__device__ float g_h[N_MAX * H];        // node features (in-place per layer)
__device__ float g_p[N_MAX * H];        // h @ W1a   (dst-role partial)
__device__ float g_q[N_MAX * H];        // h @ W1b   (src-role partial)
__device__ float g_agg[N_MAX * H];      // sum of relu(z1) (re-zeroed by upd)
__device__ float g_deg[N_MAX];          // node in-degree (recomputed each replay)
__device__ float g_pooled[G_MAX * H];   // per-graph pooled sums (re-zeroed by final)
__device__ float g_counts[G_MAX];       // per-graph node counts (re-zeroed by final)

__global__ void shim_kernel() {}        // launch-index shim for ncu window alignment

__global__ void zero_kernel(float* __restrict__ p, int n) {
    int i = blockIdx.x * blockDim.x + threadIdx.x;
    if (i < n) p[i] = 0.0f;
}

__global__ void deg_kernel(const int* __restrict__ ei, int E) {
    int e = blockIdx.x * blockDim.x + threadIdx.x;
    if (e < E) atomicAdd(&g_deg[ei[E + e]], 1.0f);
}

// ---------------------------------------------------------------------------
// Per-node GEMM1 partials:  p[n] = h[n] @ W1a (rows 0..63),
//                           q[n] = h[n] @ W1b (rows 64..127).
// One thread per node.
// ---------------------------------------------------------------------------
__global__ __launch_bounds__(128) void prep_kernel(
    const float* __restrict__ hin, const float* __restrict__ W1, int N)
{
    extern __shared__ float smem[];
    float* sWa = smem;            // 64*64
    float* sWb = sWa + H * H;     // 64*64
    for (int i = threadIdx.x; i < H * H; i += blockDim.x) sWa[i] = W1[i];
    for (int i = threadIdx.x; i < H * H; i += blockDim.x) sWb[i] = W1[H * H + i];
    __syncthreads();

    int n = blockIdx.x * blockDim.x + threadIdx.x;
    if (n >= N) return;
    const float4* hv = reinterpret_cast<const float4*>(hin + (size_t)n * H);

    float acc[H];

    // p = h @ W1a
    #pragma unroll
    for (int j = 0; j < H; j++) acc[j] = 0.0f;
    #pragma unroll 2
    for (int k4 = 0; k4 < 16; k4++) {
        float4 v4 = hv[k4];
        float v[4] = {v4.x, v4.y, v4.z, v4.w};
        const float* w = sWa + (k4 * 4) * H;
        #pragma unroll
        for (int u = 0; u < 4; u++)
            #pragma unroll
            for (int j = 0; j < H; j++)
                acc[j] += v[u] * w[u * H + j];
    }
    {
        float4* out = reinterpret_cast<float4*>(g_p + (size_t)n * H);
        #pragma unroll
        for (int t = 0; t < 16; t++)
            out[t] = make_float4(acc[4*t], acc[4*t+1], acc[4*t+2], acc[4*t+3]);
    }

    // q = h @ W1b
    #pragma unroll
    for (int j = 0; j < H; j++) acc[j] = 0.0f;
    #pragma unroll 2
    for (int k4 = 0; k4 < 16; k4++) {
        float4 v4 = hv[k4];          // L1 hit on reload
        float v[4] = {v4.x, v4.y, v4.z, v4.w};
        const float* w = sWb + (k4 * 4) * H;
        #pragma unroll
        for (int u = 0; u < 4; u++)
            #pragma unroll
            for (int j = 0; j < H; j++)
                acc[j] += v[u] * w[u * H + j];
    }
    {
        float4* out = reinterpret_cast<float4*>(g_q + (size_t)n * H);
        #pragma unroll
        for (int t = 0; t < 16; t++)
            out[t] = make_float4(acc[4*t], acc[4*t+1], acc[4*t+2], acc[4*t+3]);
    }
}

// ---------------------------------------------------------------------------
// Edge stage:  agg1[dst] += relu(p[dst] + q[src] + ea@W1c + b1)
// One thread per edge.  Only the DE=16-row GEMM remains per edge.
// ---------------------------------------------------------------------------
__global__ __launch_bounds__(256) void msg_kernel(
    const int* __restrict__ ei, const float* __restrict__ ea,
    const float* __restrict__ Wc, const float* __restrict__ b1, int E)
{
    __shared__ float sWc[DE * H];   // 16*64
    __shared__ float sb1[H];
    for (int i = threadIdx.x; i < DE * H; i += blockDim.x) sWc[i] = Wc[i];
    if (threadIdx.x < H) sb1[threadIdx.x] = b1[threadIdx.x];
    __syncthreads();

    int e = blockIdx.x * blockDim.x + threadIdx.x;
    if (e >= E) return;
    int src = ei[e];
    int dst = ei[E + e];

    const float4* eat = reinterpret_cast<const float4*>(ea + (size_t)e * DE);

    float acc[H];
    #pragma unroll
    for (int j = 0; j < H; j++) acc[j] = sb1[j];

    #pragma unroll
    for (int k4 = 0; k4 < 4; k4++) {
        float4 v4 = eat[k4];
        float v[4] = {v4.x, v4.y, v4.z, v4.w};
        const float* w = sWc + (k4 * 4) * H;
        #pragma unroll
        for (int u = 0; u < 4; u++)
            #pragma unroll
            for (int j = 0; j < H; j++)
                acc[j] += v[u] * w[u * H + j];
    }

    const float4* pv = reinterpret_cast<const float4*>(g_p + (size_t)dst * H);
    const float4* qv = reinterpret_cast<const float4*>(g_q + (size_t)src * H);
    float4* aggrow   = reinterpret_cast<float4*>(g_agg + (size_t)dst * H);

    #pragma unroll
    for (int t = 0; t < 16; t++) {
        float4 a = pv[t];
        float4 b = qv[t];
        float4 r;
        r.x = fmaxf(acc[4*t]   + a.x + b.x, 0.0f);
        r.y = fmaxf(acc[4*t+1] + a.y + b.y, 0.0f);
        r.z = fmaxf(acc[4*t+2] + a.z + b.z, 0.0f);
        r.w = fmaxf(acc[4*t+3] + a.w + b.w, 0.0f);
        atomicAdd(&aggrow[t], r);
    }
}

// ---------------------------------------------------------------------------
// Update stage (includes deferred message GEMM2).  One thread per node.
//   a2 = agg1[n] @ mW2 + deg[n]*mb2
//   t  = relu([h, a2] @ uW1 + ub1) ;  h = relu(t @ uW2 + ub2)
// Re-zeroes its g_agg row.  On the last layer also does the mean-pool adds.
// ---------------------------------------------------------------------------
__global__ __launch_bounds__(128) void upd_kernel(
    const float* __restrict__ hin,
    const float* __restrict__ mW2, const float* __restrict__ mb2,
    const float* __restrict__ W1,  const float* __restrict__ b1,
    const float* __restrict__ W2,  const float* __restrict__ b2,
    const int* __restrict__ bidx, int do_pool, int N)
{
    extern __shared__ float smem[];
    float* sM2  = smem;                 // 64*64  (message W2)
    float* sW1  = sM2 + H * H;          // 128*64
    float* sW2  = sW1 + U_IN * H;       // 64*64
    float* smb2 = sW2 + H * H;          // 64
    float* sb1  = smb2 + H;             // 64
    float* sb2  = sb1 + H;              // 64
    for (int i = threadIdx.x; i < H * H; i += blockDim.x)    sM2[i] = mW2[i];
    for (int i = threadIdx.x; i < U_IN * H; i += blockDim.x) sW1[i] = W1[i];
    for (int i = threadIdx.x; i < H * H; i += blockDim.x)    sW2[i] = W2[i];
    if (threadIdx.x < H) {
        smb2[threadIdx.x] = mb2[threadIdx.x];
        sb1[threadIdx.x]  = b1[threadIdx.x];
        sb2[threadIdx.x]  = b2[threadIdx.x];
    }
    __syncthreads();

    int n = blockIdx.x * blockDim.x + threadIdx.x;
    if (n >= N) return;

    const float4* hv = reinterpret_cast<const float4*>(hin + (size_t)n * H);
    float4*       av = reinterpret_cast<float4*>(g_agg + (size_t)n * H);
    float deg = g_deg[n];

    // phase 1: a2 = agg1 @ mW2 + deg*mb2
    float a2[H];
    #pragma unroll
    for (int j = 0; j < H; j++) a2[j] = deg * smb2[j];
    #pragma unroll 2
    for (int k4 = 0; k4 < 16; k4++) {
        float4 v4 = av[k4];
        float v[4] = {v4.x, v4.y, v4.z, v4.w};
        const float* w = sM2 + (k4 * 4) * H;
        #pragma unroll
        for (int u = 0; u < 4; u++)
            #pragma unroll
            for (int j = 0; j < H; j++)
                a2[j] += v[u] * w[u * H + j];
    }

    // re-zero this node's agg row for the next layer / next replay
    float4 z4 = make_float4(0.0f, 0.0f, 0.0f, 0.0f);
    #pragma unroll
    for (int k4 = 0; k4 < 16; k4++) av[k4] = z4;

    // phase 2: t = relu([h, a2] @ uW1 + ub1)
    float acc[H];
    #pragma unroll
    for (int j = 0; j < H; j++) acc[j] = sb1[j];

    #pragma unroll 2
    for (int k4 = 0; k4 < 16; k4++) {
        float4 v4 = hv[k4];
        float v[4] = {v4.x, v4.y, v4.z, v4.w};
        const float* w = sW1 + (k4 * 4) * H;
        #pragma unroll
        for (int u = 0; u < 4; u++)
            #pragma unroll
            for (int j = 0; j < H; j++)
                acc[j] += v[u] * w[u * H + j];
    }
    #pragma unroll 1
    for (int k = 0; k < H; k++) {
        float v = a2[k];
        const float* w = sW1 + (64 + k) * H;
        #pragma unroll
        for (int j = 0; j < H; j++)
            acc[j] += v * w[j];
    }

    #pragma unroll
    for (int j = 0; j < H; j++) acc[j] = fmaxf(acc[j], 0.0f);

    // phase 3: h = relu(t @ uW2 + ub2) ; optional pooling on last layer
    float* hout = g_h + (size_t)n * H;
    int b = do_pool ? bidx[n] : 0;
    if (do_pool) atomicAdd(&g_counts[b], 1.0f);
    float4* prow = reinterpret_cast<float4*>(g_pooled + (size_t)b * H);

    #pragma unroll 1
    for (int j2 = 0; j2 < H; j2 += 4) {
        float o0 = sb2[j2], o1 = sb2[j2 + 1], o2 = sb2[j2 + 2], o3 = sb2[j2 + 3];
        #pragma unroll
        for (int j = 0; j < H; j++) {
            float a = acc[j];
            float4 w = *reinterpret_cast<const float4*>(sW2 + j * H + j2);
            o0 += a * w.x; o1 += a * w.y; o2 += a * w.z; o3 += a * w.w;
        }
        float4 r;
        r.x = fmaxf(o0, 0.0f); r.y = fmaxf(o1, 0.0f);
        r.z = fmaxf(o2, 0.0f); r.w = fmaxf(o3, 0.0f);
        *reinterpret_cast<float4*>(hout + j2) = r;
        if (do_pool) atomicAdd(&prow[j2 / 4], r);
    }
}

// ---------------------------------------------------------------------------
// Head: out = relu(pooled/count @ lin1 + b1) @ lin2 + b2.  One thread/graph.
// Re-zeroes g_pooled / g_counts for the next replay.
// ---------------------------------------------------------------------------
__global__ void final_kernel(
    const float* __restrict__ l1w, const float* __restrict__ l1b,
    const float* __restrict__ l2w, const float* __restrict__ l2b,
    float* __restrict__ out, int G)
{
    __shared__ float sW[H * H];
    __shared__ float sb1[H];
    __shared__ float sw2[H];
    for (int i = threadIdx.x; i < H * H; i += blockDim.x) sW[i] = l1w[i];
    if (threadIdx.x < H) { sb1[threadIdx.x] = l1b[threadIdx.x]; sw2[threadIdx.x] = l2w[threadIdx.x]; }
    __syncthreads();

    int g = blockIdx.x * blockDim.x + threadIdx.x;
    if (g >= G) return;

    float inv = 1.0f / fmaxf(g_counts[g], 1.0f);
    float p[H];
    #pragma unroll
    for (int j = 0; j < H; j++) p[j] = g_pooled[g * H + j] * inv;

    g_counts[g] = 0.0f;
    #pragma unroll
    for (int j = 0; j < H; j++) g_pooled[g * H + j] = 0.0f;

    float o = l2b[0];
    #pragma unroll 1
    for (int j2 = 0; j2 < H; j2++) {
        float hsum = sb1[j2];
        #pragma unroll
        for (int j = 0; j < H; j++) hsum += p[j] * sW[j * H + j2];
        o += fmaxf(hsum, 0.0f) * sw2[j2];
    }
    out[g] = o;
}

// ---------------------------------------------------------------------------
extern "C" void kernel_launch(void* const* d_in, const int* in_sizes, int n_in,
                              void* d_out, int out_size)
{
    const float* x    = (const float*)d_in[0];
    const int*   ei   = (const int*)d_in[1];     // int32 (JAX x64 disabled)
    const float* ea   = (const float*)d_in[2];
    const int*   bidx = (const int*)d_in[3];     // int32
    const float* mW1 = (const float*)d_in[4];
    const float* mb1 = (const float*)d_in[5];
    const float* mW2 = (const float*)d_in[6];
    const float* mb2 = (const float*)d_in[7];
    const float* uW1 = (const float*)d_in[8];
    const float* ub1 = (const float*)d_in[9];
    const float* uW2 = (const float*)d_in[10];
    const float* ub2 = (const float*)d_in[11];
    const float* l1w = (const float*)d_in[12];
    const float* l1b = (const float*)d_in[13];
    const float* l2w = (const float*)d_in[14];
    const float* l2b = (const float*)d_in[15];

    int N = in_sizes[0] / H;
    int E = in_sizes[1] / 2;
    int L = in_sizes[5] / H;     // mb1 is (L, H)
    int G = out_size;            // output is (G, 1) float32

    const int M_IN = 2 * H + DE;  // 144: mW1 layer stride

    size_t prep_smem = (size_t)(2 * H * H) * sizeof(float);                        // 32 KB
    size_t upd_smem  = (size_t)(H * H + U_IN * H + H * H + 3 * H) * sizeof(float); // ~66 KB
    cudaFuncSetAttribute(prep_kernel, cudaFuncAttributeMaxDynamicSharedMemorySize, (int)prep_smem);
    cudaFuncSetAttribute(upd_kernel,  cudaFuncAttributeMaxDynamicSharedMemorySize, (int)upd_smem);

    float *h_ptr, *deg_ptr;
    cudaGetSymbolAddress((void**)&h_ptr,  g_h);
    cudaGetSymbolAddress((void**)&deg_ptr, g_deg);

    // degree (fresh each replay, deterministic)
    zero_kernel<<<(N + 255) / 256, 256>>>(deg_ptr, N);
    deg_kernel<<<(E + 255) / 256, 256>>>(ei, E);
    shim_kernel<<<1, 32>>>();
    shim_kernel<<<1, 32>>>();   // ncu -s 5 -c 1 lands on layer-0 msg_kernel

    for (int l = 0; l < L; l++) {
        const float* hsrc = (l == 0) ? x : h_ptr;
        const float* W1l  = mW1 + (size_t)l * M_IN * H;
        prep_kernel<<<(N + 127) / 128, 128, prep_smem>>>(hsrc, W1l, N);
        msg_kernel<<<(E + 255) / 256, 256>>>(
            ei, ea, W1l + (size_t)2 * H * H /* rows 128..143 */,
            mb1 + (size_t)l * H, E);
        upd_kernel<<<(N + 127) / 128, 128, upd_smem>>>(
            hsrc,
            mW2 + (size_t)l * H * H,    mb2 + (size_t)l * H,
            uW1 + (size_t)l * U_IN * H, ub1 + (size_t)l * H,
            uW2 + (size_t)l * H * H,    ub2 + (size_t)l * H,
            bidx, (l == L - 1) ? 1 : 0, N);
    }

    final_kernel<<<(G + 127) / 128, 128>>>(l1w, l1b, l2w, l2b, (float*)d_out, G);
}

// round 12
// speedup vs baseline: 3.6314x; 1.2043x over previous
#include <cuda_runtime.h>

#define H 64
#define DE 16
#define U_IN 128   // 2H

#define N_MAX 50176
#define E_MAX 802816
#define G_MAX 1024

// Scratch (static device allocations; no cudaMalloc allowed)
__device__ float g_h[N_MAX * H];        // node features (in-place per layer)
__device__ float g_p[N_MAX * H];        // h @ W1a   (dst-role partial)
__device__ float g_q[N_MAX * H];        // h @ W1b   (src-role partial)
__device__ float g_agg[N_MAX * H];      // per-node sum of relu(z1) (overwritten per layer)
__device__ int   g_deg_i[N_MAX];        // int in-degree (per launch)
__device__ int   g_cur[N_MAX];          // CSR fill cursors (per launch)
__device__ int   g_off[N_MAX + 1];      // CSR offsets
__device__ int   g_src[E_MAX];          // CSR: source node per slot
__device__ int   g_eid[E_MAX];          // CSR: edge id per slot
__device__ float g_pooled[G_MAX * H];   // per-graph pooled sums (re-zeroed by final)
__device__ float g_counts[G_MAX];       // per-graph node counts (re-zeroed by final)

// ---------------------------------------------------------------------------
// CSR build (once per launch; reused by all layers)
// ---------------------------------------------------------------------------
__global__ void zero_int_kernel(int N) {   // zero g_deg_i and g_cur
    int i = blockIdx.x * blockDim.x + threadIdx.x;
    if (i < N) { g_deg_i[i] = 0; g_cur[i] = 0; }
}

__global__ void deg_kernel(const int* __restrict__ ei, int E) {
    int e = blockIdx.x * blockDim.x + threadIdx.x;
    if (e < E) atomicAdd(&g_deg_i[ei[E + e]], 1);
}

// single-block exclusive scan of g_deg_i -> g_off  (N up to 50176)
__global__ __launch_bounds__(1024) void scan_kernel(int N) {
    __shared__ int ssum[1024];
    int t = threadIdx.x;
    int C = (N + 1023) / 1024;
    int beg = t * C;
    int end = beg + C < N ? beg + C : N;
    int s = 0;
    for (int i = beg; i < end; i++) s += g_deg_i[i];
    ssum[t] = s;
    __syncthreads();
    // Hillis-Steele inclusive scan (read-before-barrier / write-after pattern)
    for (int d = 1; d < 1024; d <<= 1) {
        int v = (t >= d) ? ssum[t - d] : 0;
        __syncthreads();
        ssum[t] += v;
        __syncthreads();
    }
    int base = (t == 0) ? 0 : ssum[t - 1];
    for (int i = beg; i < end; i++) { g_off[i] = base; base += g_deg_i[i]; }
    if (t == 1023) g_off[N] = ssum[1023];
}

__global__ void fill_kernel(const int* __restrict__ ei, int E) {
    int e = blockIdx.x * blockDim.x + threadIdx.x;
    if (e >= E) return;
    int dst = ei[E + e];
    int pos = g_off[dst] + atomicAdd(&g_cur[dst], 1);
    g_src[pos] = ei[e];
    g_eid[pos] = e;
}

// ---------------------------------------------------------------------------
// Per-node GEMM1 partials:  p[n] = h[n] @ W1a, q[n] = h[n] @ W1b.
// One thread per node.
// ---------------------------------------------------------------------------
__global__ __launch_bounds__(128) void prep_kernel(
    const float* __restrict__ hin, const float* __restrict__ W1, int N)
{
    extern __shared__ float smem[];
    float* sWa = smem;            // 64*64
    float* sWb = sWa + H * H;     // 64*64
    for (int i = threadIdx.x; i < H * H; i += blockDim.x) sWa[i] = W1[i];
    for (int i = threadIdx.x; i < H * H; i += blockDim.x) sWb[i] = W1[H * H + i];
    __syncthreads();

    int n = blockIdx.x * blockDim.x + threadIdx.x;
    if (n >= N) return;
    const float4* hv = reinterpret_cast<const float4*>(hin + (size_t)n * H);

    float acc[H];

    #pragma unroll
    for (int j = 0; j < H; j++) acc[j] = 0.0f;
    #pragma unroll 2
    for (int k4 = 0; k4 < 16; k4++) {
        float4 v4 = hv[k4];
        float v[4] = {v4.x, v4.y, v4.z, v4.w};
        const float* w = sWa + (k4 * 4) * H;
        #pragma unroll
        for (int u = 0; u < 4; u++)
            #pragma unroll
            for (int j = 0; j < H; j++)
                acc[j] += v[u] * w[u * H + j];
    }
    {
        float4* out = reinterpret_cast<float4*>(g_p + (size_t)n * H);
        #pragma unroll
        for (int t = 0; t < 16; t++)
            out[t] = make_float4(acc[4*t], acc[4*t+1], acc[4*t+2], acc[4*t+3]);
    }

    #pragma unroll
    for (int j = 0; j < H; j++) acc[j] = 0.0f;
    #pragma unroll 2
    for (int k4 = 0; k4 < 16; k4++) {
        float4 v4 = hv[k4];
        float v[4] = {v4.x, v4.y, v4.z, v4.w};
        const float* w = sWb + (k4 * 4) * H;
        #pragma unroll
        for (int u = 0; u < 4; u++)
            #pragma unroll
            for (int j = 0; j < H; j++)
                acc[j] += v[u] * w[u * H + j];
    }
    {
        float4* out = reinterpret_cast<float4*>(g_q + (size_t)n * H);
        #pragma unroll
        for (int t = 0; t < 16; t++)
            out[t] = make_float4(acc[4*t], acc[4*t+1], acc[4*t+2], acc[4*t+3]);
    }
}

// ---------------------------------------------------------------------------
// Edge stage via CSR: one WARP per destination node, NO atomics.
//   agg[n] = sum_{e in csr[n]} relu(p[n] + q[src_e] + ea_e @ Wc + b1)
// Lane owns 2 output columns; Wc columns live in registers across the loop.
// ---------------------------------------------------------------------------
__global__ __launch_bounds__(256) void msg_kernel(
    const float* __restrict__ ea,
    const float* __restrict__ Wc, const float* __restrict__ b1, int N)
{
    int warp = (blockIdx.x * blockDim.x + threadIdx.x) >> 5;
    int lane = threadIdx.x & 31;
    if (warp >= N) return;
    int n = warp;
    int c = 2 * lane;

    float2 wc[DE];
    #pragma unroll
    for (int u = 0; u < DE; u++)
        wc[u] = *reinterpret_cast<const float2*>(Wc + u * H + c);

    float2 bb = *reinterpret_cast<const float2*>(b1 + c);
    float2 pp = *reinterpret_cast<const float2*>(g_p + (size_t)n * H + c);
    float base0 = pp.x + bb.x;
    float base1 = pp.y + bb.y;

    float acc0 = 0.0f, acc1 = 0.0f;
    int kbeg = g_off[n], kend = g_off[n + 1];

    for (int k = kbeg; k < kend; k++) {
        int src = g_src[k];
        int e   = g_eid[k];
        float2 q = *reinterpret_cast<const float2*>(g_q + (size_t)src * H + c);
        const float4* eat = reinterpret_cast<const float4*>(ea + (size_t)e * DE);
        float4 e0 = eat[0], e1 = eat[1], e2 = eat[2], e3 = eat[3];
        float ev[DE] = {e0.x, e0.y, e0.z, e0.w,  e1.x, e1.y, e1.z, e1.w,
                        e2.x, e2.y, e2.z, e2.w,  e3.x, e3.y, e3.z, e3.w};
        float z0 = base0 + q.x;
        float z1 = base1 + q.y;
        #pragma unroll
        for (int u = 0; u < DE; u++) {
            z0 += ev[u] * wc[u].x;
            z1 += ev[u] * wc[u].y;
        }
        acc0 += fmaxf(z0, 0.0f);
        acc1 += fmaxf(z1, 0.0f);
    }

    *reinterpret_cast<float2*>(g_agg + (size_t)n * H + c) = make_float2(acc0, acc1);
}

// ---------------------------------------------------------------------------
// Update stage (includes deferred message GEMM2).  One thread per node.
//   a2 = agg[n] @ mW2 + deg[n]*mb2
//   t  = relu([h, a2] @ uW1 + ub1) ;  h = relu(t @ uW2 + ub2)
// On the last layer also does the mean-pool adds.
// ---------------------------------------------------------------------------
__global__ __launch_bounds__(128) void upd_kernel(
    const float* __restrict__ hin,
    const float* __restrict__ mW2, const float* __restrict__ mb2,
    const float* __restrict__ W1,  const float* __restrict__ b1,
    const float* __restrict__ W2,  const float* __restrict__ b2,
    const int* __restrict__ bidx, int do_pool, int N)
{
    extern __shared__ float smem[];
    float* sM2  = smem;                 // 64*64  (message W2)
    float* sW1  = sM2 + H * H;          // 128*64
    float* sW2  = sW1 + U_IN * H;       // 64*64
    float* smb2 = sW2 + H * H;          // 64
    float* sb1  = smb2 + H;             // 64
    float* sb2  = sb1 + H;              // 64
    for (int i = threadIdx.x; i < H * H; i += blockDim.x)    sM2[i] = mW2[i];
    for (int i = threadIdx.x; i < U_IN * H; i += blockDim.x) sW1[i] = W1[i];
    for (int i = threadIdx.x; i < H * H; i += blockDim.x)    sW2[i] = W2[i];
    if (threadIdx.x < H) {
        smb2[threadIdx.x] = mb2[threadIdx.x];
        sb1[threadIdx.x]  = b1[threadIdx.x];
        sb2[threadIdx.x]  = b2[threadIdx.x];
    }
    __syncthreads();

    int n = blockIdx.x * blockDim.x + threadIdx.x;
    if (n >= N) return;

    const float4* hv = reinterpret_cast<const float4*>(hin + (size_t)n * H);
    const float4* av = reinterpret_cast<const float4*>(g_agg + (size_t)n * H);
    float deg = (float)(g_off[n + 1] - g_off[n]);

    // phase 1: a2 = agg @ mW2 + deg*mb2
    float a2[H];
    #pragma unroll
    for (int j = 0; j < H; j++) a2[j] = deg * smb2[j];
    #pragma unroll 2
    for (int k4 = 0; k4 < 16; k4++) {
        float4 v4 = av[k4];
        float v[4] = {v4.x, v4.y, v4.z, v4.w};
        const float* w = sM2 + (k4 * 4) * H;
        #pragma unroll
        for (int u = 0; u < 4; u++)
            #pragma unroll
            for (int j = 0; j < H; j++)
                a2[j] += v[u] * w[u * H + j];
    }

    // phase 2: t = relu([h, a2] @ uW1 + ub1)
    float acc[H];
    #pragma unroll
    for (int j = 0; j < H; j++) acc[j] = sb1[j];

    #pragma unroll 2
    for (int k4 = 0; k4 < 16; k4++) {
        float4 v4 = hv[k4];
        float v[4] = {v4.x, v4.y, v4.z, v4.w};
        const float* w = sW1 + (k4 * 4) * H;
        #pragma unroll
        for (int u = 0; u < 4; u++)
            #pragma unroll
            for (int j = 0; j < H; j++)
                acc[j] += v[u] * w[u * H + j];
    }
    #pragma unroll 1
    for (int k = 0; k < H; k++) {
        float v = a2[k];
        const float* w = sW1 + (64 + k) * H;
        #pragma unroll
        for (int j = 0; j < H; j++)
            acc[j] += v * w[j];
    }

    #pragma unroll
    for (int j = 0; j < H; j++) acc[j] = fmaxf(acc[j], 0.0f);

    // phase 3: h = relu(t @ uW2 + ub2) ; optional pooling on last layer
    float* hout = g_h + (size_t)n * H;
    int b = do_pool ? bidx[n] : 0;
    if (do_pool) atomicAdd(&g_counts[b], 1.0f);
    float4* prow = reinterpret_cast<float4*>(g_pooled + (size_t)b * H);

    #pragma unroll 1
    for (int j2 = 0; j2 < H; j2 += 4) {
        float o0 = sb2[j2], o1 = sb2[j2 + 1], o2 = sb2[j2 + 2], o3 = sb2[j2 + 3];
        #pragma unroll
        for (int j = 0; j < H; j++) {
            float a = acc[j];
            float4 w = *reinterpret_cast<const float4*>(sW2 + j * H + j2);
            o0 += a * w.x; o1 += a * w.y; o2 += a * w.z; o3 += a * w.w;
        }
        float4 r;
        r.x = fmaxf(o0, 0.0f); r.y = fmaxf(o1, 0.0f);
        r.z = fmaxf(o2, 0.0f); r.w = fmaxf(o3, 0.0f);
        *reinterpret_cast<float4*>(hout + j2) = r;
        if (do_pool) atomicAdd(&prow[j2 / 4], r);
    }
}

// ---------------------------------------------------------------------------
// Head: out = relu(pooled/count @ lin1 + b1) @ lin2 + b2.  One thread/graph.
// Re-zeroes g_pooled / g_counts for the next replay.
// ---------------------------------------------------------------------------
__global__ void final_kernel(
    const float* __restrict__ l1w, const float* __restrict__ l1b,
    const float* __restrict__ l2w, const float* __restrict__ l2b,
    float* __restrict__ out, int G)
{
    __shared__ float sW[H * H];
    __shared__ float sb1[H];
    __shared__ float sw2[H];
    for (int i = threadIdx.x; i < H * H; i += blockDim.x) sW[i] = l1w[i];
    if (threadIdx.x < H) { sb1[threadIdx.x] = l1b[threadIdx.x]; sw2[threadIdx.x] = l2w[threadIdx.x]; }
    __syncthreads();

    int g = blockIdx.x * blockDim.x + threadIdx.x;
    if (g >= G) return;

    float inv = 1.0f / fmaxf(g_counts[g], 1.0f);
    float p[H];
    #pragma unroll
    for (int j = 0; j < H; j++) p[j] = g_pooled[g * H + j] * inv;

    g_counts[g] = 0.0f;
    #pragma unroll
    for (int j = 0; j < H; j++) g_pooled[g * H + j] = 0.0f;

    float o = l2b[0];
    #pragma unroll 1
    for (int j2 = 0; j2 < H; j2++) {
        float hsum = sb1[j2];
        #pragma unroll
        for (int j = 0; j < H; j++) hsum += p[j] * sW[j * H + j2];
        o += fmaxf(hsum, 0.0f) * sw2[j2];
    }
    out[g] = o;
}

// ---------------------------------------------------------------------------
extern "C" void kernel_launch(void* const* d_in, const int* in_sizes, int n_in,
                              void* d_out, int out_size)
{
    const float* x    = (const float*)d_in[0];
    const int*   ei   = (const int*)d_in[1];     // int32 (JAX x64 disabled)
    const float* ea   = (const float*)d_in[2];
    const int*   bidx = (const int*)d_in[3];     // int32
    const float* mW1 = (const float*)d_in[4];
    const float* mb1 = (const float*)d_in[5];
    const float* mW2 = (const float*)d_in[6];
    const float* mb2 = (const float*)d_in[7];
    const float* uW1 = (const float*)d_in[8];
    const float* ub1 = (const float*)d_in[9];
    const float* uW2 = (const float*)d_in[10];
    const float* ub2 = (const float*)d_in[11];
    const float* l1w = (const float*)d_in[12];
    const float* l1b = (const float*)d_in[13];
    const float* l2w = (const float*)d_in[14];
    const float* l2b = (const float*)d_in[15];

    int N = in_sizes[0] / H;
    int E = in_sizes[1] / 2;
    int L = in_sizes[5] / H;     // mb1 is (L, H)
    int G = out_size;            // output is (G, 1) float32

    const int M_IN = 2 * H + DE;  // 144: mW1 layer stride

    size_t prep_smem = (size_t)(2 * H * H) * sizeof(float);                        // 32 KB
    size_t upd_smem  = (size_t)(H * H + U_IN * H + H * H + 3 * H) * sizeof(float); // ~66 KB
    cudaFuncSetAttribute(prep_kernel, cudaFuncAttributeMaxDynamicSharedMemorySize, (int)prep_smem);
    cudaFuncSetAttribute(upd_kernel,  cudaFuncAttributeMaxDynamicSharedMemorySize, (int)upd_smem);

    float* h_ptr;
    cudaGetSymbolAddress((void**)&h_ptr, g_h);

    // CSR build (once per launch; deterministic work, bucket order arbitrary)
    zero_int_kernel<<<(N + 255) / 256, 256>>>(N);
    deg_kernel<<<(E + 255) / 256, 256>>>(ei, E);
    scan_kernel<<<1, 1024>>>(N);
    fill_kernel<<<(E + 255) / 256, 256>>>(ei, E);
    // launch indices: 1 zero, 2 deg, 3 scan, 4 fill, 5 prep0 -> ncu (-s 5) captures msg0

    for (int l = 0; l < L; l++) {
        const float* hsrc = (l == 0) ? x : h_ptr;
        const float* W1l  = mW1 + (size_t)l * M_IN * H;
        prep_kernel<<<(N + 127) / 128, 128, prep_smem>>>(hsrc, W1l, N);
        msg_kernel<<<(N * 32 + 255) / 256, 256>>>(
            ea, W1l + (size_t)2 * H * H /* rows 128..143 */,
            mb1 + (size_t)l * H, N);
        upd_kernel<<<(N + 127) / 128, 128, upd_smem>>>(
            hsrc,
            mW2 + (size_t)l * H * H,    mb2 + (size_t)l * H,
            uW1 + (size_t)l * U_IN * H, ub1 + (size_t)l * H,
            uW2 + (size_t)l * H * H,    ub2 + (size_t)l * H,
            bidx, (l == L - 1) ? 1 : 0, N);
    }

    final_kernel<<<(G + 127) / 128, 128>>>(l1w, l1b, l2w, l2b, (float*)d_out, G);
}